// round 12
// baseline (speedup 1.0000x reference)
#include <cuda_runtime.h>
#include <cuda_fp16.h>
#include <math.h>
#include <stdint.h>

#define NN_NODES 100000
#define EE_EDGES 3200000
#define FDIM 256
#define CDIM 64
#define LN_EPS 1e-5

// ---------------- scratch (static device globals; no allocation) ----------------
__device__ int    g_deg_s[NN_NODES];
__device__ int    g_deg_d[NN_NODES];
__device__ float  g_norm_s[NN_NODES];
__device__ float  g_norm_d[NN_NODES];
__device__ int    g_row_off[NN_NODES + 1];
__device__ int    g_cursor[NN_NODES];
__device__ int    g_col[EE_EDGES];
__device__ __half g_x16[(size_t)NN_NODES * FDIM];   // fp16 input features
__device__ __half g_h16[(size_t)NN_NODES * FDIM];   // fp16 hidden (gather source + L3 A)
__device__ __half g_agg16[(size_t)NN_NODES * FDIM]; // fp16 aggregate (GEMM A)
__device__ __half g_t16[(size_t)NN_NODES * CDIM];   // fp16 layer-3 GEMM out
__device__ double g_stats[2];   // sum, sumsq
__device__ float  g_ln[2];      // mu, inv_std
__device__ float  g_csum[CDIM]; // column sums of W2 (layer-3 LN fold)
// pre-split, pre-transposed weights: [n][K] fp16 hi/lo
__device__ __half g_w0h[FDIM * FDIM], g_w0l[FDIM * FDIM];
__device__ __half g_w1h[FDIM * FDIM], g_w1l[FDIM * FDIM];
__device__ __half g_w2h[CDIM * FDIM], g_w2l[CDIM * FDIM];

// ---------------- setup kernels ----------------
__global__ void k_init() {
    int i = blockIdx.x * blockDim.x + threadIdx.x;
    if (i < NN_NODES) { g_deg_s[i] = 0; g_deg_d[i] = 0; }
    if (i == 0) { g_stats[0] = 0.0; g_stats[1] = 0.0; }
}

__global__ void k_degrees(const int* __restrict__ src, const int* __restrict__ dst) {
    int e = blockIdx.x * blockDim.x + threadIdx.x;
    if (e < EE_EDGES) {
        atomicAdd(&g_deg_s[src[e]], 1);
        atomicAdd(&g_deg_d[dst[e]], 1);
    }
}

__global__ void k_scan() {
    const int T = 1024;
    int t = threadIdx.x;
    const int chunk = (NN_NODES + T - 1) / T;
    int beg = t * chunk;
    int end = min(beg + chunk, NN_NODES);
    int local = 0;
    for (int i = beg; i < end; i++) local += g_deg_d[i];

    __shared__ int sh[T];
    sh[t] = local;
    __syncthreads();
    for (int off = 1; off < T; off <<= 1) {
        int v = (t >= off) ? sh[t - off] : 0;
        __syncthreads();
        sh[t] += v;
        __syncthreads();
    }
    int run = sh[t] - local;
    for (int i = beg; i < end; i++) {
        g_row_off[i] = run;
        g_cursor[i] = run;
        run += g_deg_d[i];
    }
    if (t == T - 1) g_row_off[NN_NODES] = sh[T - 1];

    for (int i = beg; i < end; i++) {
        g_norm_s[i] = rsqrtf((float)max(g_deg_s[i], 1));
        g_norm_d[i] = rsqrtf((float)max(g_deg_d[i], 1));
    }
}

__global__ void k_fill(const int* __restrict__ src, const int* __restrict__ dst) {
    int e = blockIdx.x * blockDim.x + threadIdx.x;
    if (e < EE_EDGES) {
        int p = atomicAdd(&g_cursor[dst[e]], 1);
        g_col[p] = src[e];
    }
}

// fp32 -> fp16 convert (8 elements/thread)
__global__ void k_cvt(const float* __restrict__ x, __half* __restrict__ y, int n8) {
    int i = blockIdx.x * blockDim.x + threadIdx.x;
    if (i >= n8) return;
    float4 a = reinterpret_cast<const float4*>(x)[i * 2];
    float4 b = reinterpret_cast<const float4*>(x)[i * 2 + 1];
    __half2 h[4];
    h[0] = __floats2half2_rn(a.x, a.y);
    h[1] = __floats2half2_rn(a.z, a.w);
    h[2] = __floats2half2_rn(b.x, b.y);
    h[3] = __floats2half2_rn(b.z, b.w);
    reinterpret_cast<float4*>(y)[i] = *reinterpret_cast<float4*>(h);
}

// pre-split + transpose weights: W[K][N] fp32 -> Wh/Wl[N][K] fp16
__global__ void k_prep_w(const float* __restrict__ W, __half* __restrict__ Wh,
                         __half* __restrict__ Wl, int K, int N) {
    int idx = blockIdx.x * blockDim.x + threadIdx.x;
    if (idx >= K * N) return;
    int k = idx / N, n = idx % N;
    float x = W[idx];
    __half h = __float2half_rn(x);
    __half l = __float2half_rn(x - __half2float(h));
    Wh[n * K + k] = h;
    Wl[n * K + k] = l;
}

// column sums of W2 [FDIM][CDIM] for layer-3 LN fold
__global__ void k_csum(const float* __restrict__ W2) {
    int n = threadIdx.x;
    if (n >= CDIM) return;
    float s = 0.f;
    for (int k = 0; k < FDIM; k++) s += W2[k * CDIM + n];
    g_csum[n] = s;
}

// ---------------- SpMM: pull (warp per dst row), fp16 in/out, fp32 accum ----------------
// batch-of-16 explicit load phase for MLP=16
template <bool LN>
__global__ void k_spmm256(const __half* __restrict__ hin, __half* __restrict__ out) {
    int gw = (blockIdx.x * blockDim.x + threadIdx.x) >> 5;
    int lane = threadIdx.x & 31;
    if (gw >= NN_NODES) return;

    float mu = 0.f, inv = 1.f;
    if (LN) { mu = g_ln[0]; inv = g_ln[1]; }

    int s0 = g_row_off[gw], s1 = g_row_off[gw + 1];
    float acc[8];
#pragma unroll
    for (int t = 0; t < 8; t++) acc[t] = 0.f;

    const float4* __restrict__ h4 = reinterpret_cast<const float4*>(hin); // 8 halves each

    for (int base = s0; base < s1; base += 32) {
        int kk = base + lane;
        int j = 0; float sc = 0.f;
        if (kk < s1) { j = g_col[kk]; sc = g_norm_s[j]; }
        int cnt = min(32, s1 - base);

        for (int i0 = 0; i0 < cnt; i0 += 16) {
            int m = min(16, cnt - i0);
            float4 raw[16];
            // load phase: up to 16 independent 16B gathers in flight
#pragma unroll
            for (int t = 0; t < 16; t++) {
                if (t < m) {
                    int jj = __shfl_sync(0xffffffffu, j, i0 + t);
                    raw[t] = h4[(size_t)jj * 32 + lane];
                }
            }
            // accumulate phase
#pragma unroll
            for (int t = 0; t < 16; t++) {
                if (t < m) {
                    float sj = __shfl_sync(0xffffffffu, sc, i0 + t);
                    const __half2* hp = reinterpret_cast<const __half2*>(&raw[t]);
                    float2 f0 = __half22float2(hp[0]);
                    float2 f1 = __half22float2(hp[1]);
                    float2 f2 = __half22float2(hp[2]);
                    float2 f3 = __half22float2(hp[3]);
                    float sv = LN ? (sj * inv) : sj;
                    if (LN) {
                        acc[0] = fmaf(f0.x - mu, sv, acc[0]); acc[1] = fmaf(f0.y - mu, sv, acc[1]);
                        acc[2] = fmaf(f1.x - mu, sv, acc[2]); acc[3] = fmaf(f1.y - mu, sv, acc[3]);
                        acc[4] = fmaf(f2.x - mu, sv, acc[4]); acc[5] = fmaf(f2.y - mu, sv, acc[5]);
                        acc[6] = fmaf(f3.x - mu, sv, acc[6]); acc[7] = fmaf(f3.y - mu, sv, acc[7]);
                    } else {
                        acc[0] = fmaf(f0.x, sv, acc[0]); acc[1] = fmaf(f0.y, sv, acc[1]);
                        acc[2] = fmaf(f1.x, sv, acc[2]); acc[3] = fmaf(f1.y, sv, acc[3]);
                        acc[4] = fmaf(f2.x, sv, acc[4]); acc[5] = fmaf(f2.y, sv, acc[5]);
                        acc[6] = fmaf(f3.x, sv, acc[6]); acc[7] = fmaf(f3.y, sv, acc[7]);
                    }
                }
            }
        }
    }
    float nd = g_norm_d[gw];
    __half2 hv[4];
    hv[0] = __floats2half2_rn(acc[0] * nd, acc[1] * nd);
    hv[1] = __floats2half2_rn(acc[2] * nd, acc[3] * nd);
    hv[2] = __floats2half2_rn(acc[4] * nd, acc[5] * nd);
    hv[3] = __floats2half2_rn(acc[6] * nd, acc[7] * nd);
    reinterpret_cast<float4*>(out)[(size_t)gw * 32 + lane] = *reinterpret_cast<float4*>(hv);
}

// ---------------- SpMM 64-wide (final layer, fp16 gather, with bias) ----------------
__global__ void k_spmm64(const __half* __restrict__ tin, const float* __restrict__ bias,
                         float* __restrict__ out) {
    int gw = (blockIdx.x * blockDim.x + threadIdx.x) >> 5;
    int lane = threadIdx.x & 31;
    if (gw >= NN_NODES) return;

    int s0 = g_row_off[gw], s1 = g_row_off[gw + 1];
    float2 a = make_float2(0.f, 0.f);
    const __half2* __restrict__ t2 = reinterpret_cast<const __half2*>(tin);

    for (int base = s0; base < s1; base += 32) {
        int kk = base + lane;
        int j = 0; float sc = 0.f;
        if (kk < s1) { j = g_col[kk]; sc = g_norm_s[j]; }
        int cnt = min(32, s1 - base);

        for (int i0 = 0; i0 < cnt; i0 += 16) {
            int m = min(16, cnt - i0);
            __half2 raw[16];
#pragma unroll
            for (int t = 0; t < 16; t++) {
                if (t < m) {
                    int jj = __shfl_sync(0xffffffffu, j, i0 + t);
                    raw[t] = t2[(size_t)jj * (CDIM / 2) + lane];
                }
            }
#pragma unroll
            for (int t = 0; t < 16; t++) {
                if (t < m) {
                    float sj = __shfl_sync(0xffffffffu, sc, i0 + t);
                    float2 v = __half22float2(raw[t]);
                    a.x = fmaf(v.x, sj, a.x);
                    a.y = fmaf(v.y, sj, a.y);
                }
            }
        }
    }
    float nd = g_norm_d[gw];
    float2 b = reinterpret_cast<const float2*>(bias)[lane];
    float2 o;
    o.x = fmaf(a.x, nd, b.x);
    o.y = fmaf(a.y, nd, b.y);
    reinterpret_cast<float2*>(out)[(size_t)gw * (CDIM / 2) + lane] = o;
}

// ---------------- fp16 tensor-core GEMM (R9: scalar frag loads, single buffer) ----------------
// C = A @ W, A fp16 (pure copy), W = Wh + Wl pre-split (exact).
// 2 MMAs per frag pair: Ah*Bh + Ah*Bl.
template <int BM, int BN, int WM, int WN, bool BIAS_RELU, bool STATS, bool LNFOLD,
          bool C_HALF>
__global__ void __launch_bounds__(256, 2)
k_gemm16(const __half* __restrict__ A16,
         const __half* __restrict__ Bh_g,   // [n][K] fp16 hi
         const __half* __restrict__ Bl_g,   // [n][K] fp16 lo
         const float* __restrict__ bias, void* __restrict__ Cp,
         int M, int Nn, int K) {
    constexpr int BK = 32;
    constexpr int LDA = BK + 8;          // halves; pitch 80B
    constexpr int LDB = BK + 8;
    constexpr int NWARP = (BM / WM) * (BN / WN);
    constexpr int NT = NWARP * 32;
    constexpr int MFRAG = WM / 16;
    constexpr int NFRAG = WN / 8;
    static_assert(BM * (BK / 16) == NT, "A staging map");

    __shared__ __half As[BM * LDA];
    __shared__ __half Bs_h[BN * LDB];
    __shared__ __half Bs_l[BN * LDB];

    const int tid  = threadIdx.x;
    const int lane = tid & 31;
    const int warp = tid >> 5;
    const int wm0 = (warp / (BN / WN)) * WM;
    const int wn0 = (warp % (BN / WN)) * WN;
    const int bm0 = blockIdx.x * BM;
    const int bn0 = blockIdx.y * BN;

    float acc[MFRAG][NFRAG][4];
#pragma unroll
    for (int i = 0; i < MFRAG; i++)
#pragma unroll
        for (int j = 0; j < NFRAG; j++)
#pragma unroll
            for (int q = 0; q < 4; q++) acc[i][j][q] = 0.f;

    const int gr = lane >> 2;
    const int gc = lane & 3;

    // A staging: 2 threads per row, 16 consecutive halves (32B) each — pure copy
    const int am = tid >> 1;
    const int aq = tid & 1;
    const int arow = bm0 + am;
    const bool aok = arow < M;

    for (int k0 = 0; k0 < K; k0 += BK) {
        // ---- stage A: float4 copies ----
        {
            uint4 v0 = make_uint4(0u, 0u, 0u, 0u), v1 = v0;
            if (aok) {
                const uint4* s = reinterpret_cast<const uint4*>(&A16[(size_t)arow * K + k0 + aq * 16]);
                v0 = s[0]; v1 = s[1];
            }
            uint4* pa = reinterpret_cast<uint4*>(&As[am * LDA + aq * 16]);
            pa[0] = v0; pa[1] = v1;
        }
        // ---- stage B: float4 copies from pre-split [n][K] fp16 ----
        constexpr int B4 = BN * BK / 8;   // float4 count
#pragma unroll
        for (int p = 0; p < B4 / NT; p++) {
            int idx = tid + p * NT;
            int n = idx / (BK / 8), seg = idx % (BK / 8);
            size_t goff = (size_t)(bn0 + n) * K + k0 + seg * 8;
            *reinterpret_cast<uint4*>(&Bs_h[n * LDB + seg * 8]) =
                *reinterpret_cast<const uint4*>(&Bh_g[goff]);
            *reinterpret_cast<uint4*>(&Bs_l[n * LDB + seg * 8]) =
                *reinterpret_cast<const uint4*>(&Bl_g[goff]);
        }
        __syncthreads();

#pragma unroll
        for (int ks = 0; ks < BK / 16; ks++) {
            const int kb = ks * 16;
            unsigned a[MFRAG][4];
#pragma unroll
            for (int mi = 0; mi < MFRAG; mi++) {
                int r = wm0 + mi * 16 + gr;
                a[mi][0] = *reinterpret_cast<const unsigned*>(&As[r * LDA + kb + 2 * gc]);
                a[mi][1] = *reinterpret_cast<const unsigned*>(&As[(r + 8) * LDA + kb + 2 * gc]);
                a[mi][2] = *reinterpret_cast<const unsigned*>(&As[r * LDA + kb + 2 * gc + 8]);
                a[mi][3] = *reinterpret_cast<const unsigned*>(&As[(r + 8) * LDA + kb + 2 * gc + 8]);
            }
            unsigned bh[NFRAG][2], bl[NFRAG][2];
#pragma unroll
            for (int ni = 0; ni < NFRAG; ni++) {
                int c = wn0 + ni * 8 + gr;
                bh[ni][0] = *reinterpret_cast<const unsigned*>(&Bs_h[c * LDB + kb + 2 * gc]);
                bh[ni][1] = *reinterpret_cast<const unsigned*>(&Bs_h[c * LDB + kb + 2 * gc + 8]);
                bl[ni][0] = *reinterpret_cast<const unsigned*>(&Bs_l[c * LDB + kb + 2 * gc]);
                bl[ni][1] = *reinterpret_cast<const unsigned*>(&Bs_l[c * LDB + kb + 2 * gc + 8]);
            }
#pragma unroll
            for (int mi = 0; mi < MFRAG; mi++)
#pragma unroll
                for (int ni = 0; ni < NFRAG; ni++) {
#define MMA_F16(B0,B1)                                                           \
    asm volatile("mma.sync.aligned.m16n8k16.row.col.f32.f16.f16.f32 "            \
                 "{%0,%1,%2,%3}, {%4,%5,%6,%7}, {%8,%9}, {%0,%1,%2,%3};"         \
                 : "+f"(acc[mi][ni][0]), "+f"(acc[mi][ni][1]),                   \
                   "+f"(acc[mi][ni][2]), "+f"(acc[mi][ni][3])                    \
                 : "r"(a[mi][0]), "r"(a[mi][1]), "r"(a[mi][2]), "r"(a[mi][3]),   \
                   "r"(B0), "r"(B1))
                    MMA_F16(bl[ni][0], bl[ni][1]);
                    MMA_F16(bh[ni][0], bh[ni][1]);
#undef MMA_F16
                }
        }
        __syncthreads();
    }

    // ---- epilogue ----
    float mu = 0.f, inv = 1.f;
    if (LNFOLD) { mu = g_ln[0]; inv = g_ln[1]; }
    double psum = 0.0, psq = 0.0;
#pragma unroll
    for (int mi = 0; mi < MFRAG; mi++) {
#pragma unroll
        for (int ni = 0; ni < NFRAG; ni++) {
            int c0 = bn0 + wn0 + ni * 8 + gc * 2;
            float2 bb = make_float2(0.f, 0.f);
            if (BIAS_RELU) bb = *reinterpret_cast<const float2*>(&bias[c0]);
            float2 cs = make_float2(0.f, 0.f);
            if (LNFOLD) cs = *reinterpret_cast<const float2*>(&g_csum[c0]);
#pragma unroll
            for (int hf = 0; hf < 2; hf++) {
                int row = bm0 + wm0 + mi * 16 + gr + hf * 8;
                if (row >= M) continue;
                float x = acc[mi][ni][hf * 2 + 0];
                float y = acc[mi][ni][hf * 2 + 1];
                if (BIAS_RELU) {
                    x = fmaxf(x + bb.x, 0.f);
                    y = fmaxf(y + bb.y, 0.f);
                }
                if (LNFOLD) {
                    x = x * inv - mu * inv * cs.x;
                    y = y * inv - mu * inv * cs.y;
                }
                if (C_HALF) {
                    __half* C16 = (__half*)Cp;
                    *reinterpret_cast<__half2*>(&C16[(size_t)row * Nn + c0]) =
                        __floats2half2_rn(x, y);
                } else {
                    float* Cf = (float*)Cp;
                    *reinterpret_cast<float2*>(&Cf[(size_t)row * Nn + c0]) = make_float2(x, y);
                }
                if (STATS) {
                    psum += (double)x + (double)y;
                    psq  += (double)x * x + (double)y * y;
                }
            }
        }
    }

    if (STATS) {
#pragma unroll
        for (int off = 16; off > 0; off >>= 1) {
            psum += __shfl_down_sync(0xffffffffu, psum, off);
            psq  += __shfl_down_sync(0xffffffffu, psq, off);
        }
        if (lane == 0) {
            atomicAdd(&g_stats[0], psum);
            atomicAdd(&g_stats[1], psq);
        }
    }
}

__global__ void k_finalize(double count) {
    double s = g_stats[0], ss = g_stats[1];
    double mu = s / count;
    double var = ss / count - mu * mu;
    g_ln[0] = (float)mu;
    g_ln[1] = (float)(1.0 / sqrt(var + (double)LN_EPS));
    g_stats[0] = 0.0;
    g_stats[1] = 0.0;
}

// ---------------- launch ----------------
extern "C" void kernel_launch(void* const* d_in, const int* in_sizes, int n_in,
                              void* d_out, int out_size) {
    const float* feat = (const float*)d_in[0];
    const int*   src  = (const int*)d_in[1];
    const int*   dst  = (const int*)d_in[2];
    const float* W0   = (const float*)d_in[3];
    const float* b0   = (const float*)d_in[4];
    const float* W1   = (const float*)d_in[5];
    const float* b1   = (const float*)d_in[6];
    const float* W2   = (const float*)d_in[7];
    const float* b2   = (const float*)d_in[8];
    float* out = (float*)d_out;

    __half *x16, *h16, *agg16, *tbuf;
    __half *w0h, *w0l, *w1h, *w1l, *w2h, *w2l;
    cudaGetSymbolAddress((void**)&x16, g_x16);
    cudaGetSymbolAddress((void**)&h16, g_h16);
    cudaGetSymbolAddress((void**)&agg16, g_agg16);
    cudaGetSymbolAddress((void**)&tbuf, g_t16);
    cudaGetSymbolAddress((void**)&w0h, g_w0h);
    cudaGetSymbolAddress((void**)&w0l, g_w0l);
    cudaGetSymbolAddress((void**)&w1h, g_w1h);
    cudaGetSymbolAddress((void**)&w1l, g_w1l);
    cudaGetSymbolAddress((void**)&w2h, g_w2h);
    cudaGetSymbolAddress((void**)&w2l, g_w2l);

    const int NB_N = (NN_NODES + 255) / 256;
    const int NB_E = (EE_EDGES + 255) / 256;
    const int NB_W = (NN_NODES * 32 + 255) / 256;  // warp per row
    const int NB_C = ((NN_NODES * FDIM / 8) + 255) / 256;

    // setup: degrees, norms, CSR (by dst), fp16 features, split weights
    k_init<<<NB_N, 256>>>();
    k_degrees<<<NB_E, 256>>>(src, dst);
    k_scan<<<1, 1024>>>();
    k_fill<<<NB_E, 256>>>(src, dst);
    k_cvt<<<NB_C, 256>>>(feat, x16, NN_NODES * FDIM / 8);
    k_prep_w<<<(FDIM * FDIM + 255) / 256, 256>>>(W0, w0h, w0l, FDIM, FDIM);
    k_prep_w<<<(FDIM * FDIM + 255) / 256, 256>>>(W1, w1h, w1l, FDIM, FDIM);
    k_prep_w<<<(FDIM * CDIM + 255) / 256, 256>>>(W2, w2h, w2l, FDIM, CDIM);
    k_csum<<<1, CDIM>>>(W2);

    const int GM = (NN_NODES + 127) / 128;
    const double cnt = (double)NN_NODES * FDIM;

    // layer 1: agg16 = fp16(DAD*X) ; h1 = relu(agg@W0 + b0) (+stats), fp16
    k_spmm256<false><<<NB_W, 256>>>(x16, agg16);
    k_gemm16<128, 128, 64, 32, true, true, false, true>
        <<<dim3(GM, FDIM / 128), 256>>>(agg16, w0h, w0l, b0, h16, NN_NODES, FDIM, FDIM);
    k_finalize<<<1, 1>>>(cnt);

    // layer 2: agg16 = fp16(DAD*LN(h1)) ; h2 = relu(agg@W1 + b1) (+stats), fp16
    k_spmm256<true><<<NB_W, 256>>>(h16, agg16);
    k_gemm16<128, 128, 64, 32, true, true, false, true>
        <<<dim3(GM, FDIM / 128), 256>>>(agg16, w1h, w1l, b1, h16, NN_NODES, FDIM, FDIM);
    k_finalize<<<1, 1>>>(cnt);

    // layer 3: t16 = fp16(LN(h2)@W2) via epilogue fold ; out = DAD*t + b2
    k_gemm16<128, 64, 64, 16, false, false, true, true>
        <<<dim3(GM, 1), 256>>>(h16, w2h, w2l, nullptr, tbuf, NN_NODES, CDIM, FDIM);
    k_spmm64<<<NB_W, 256>>>(tbuf, b2, out);
}

// round 13
// speedup vs baseline: 1.2668x; 1.2668x over previous
#include <cuda_runtime.h>
#include <cuda_fp16.h>
#include <math.h>
#include <stdint.h>

#define NN_NODES 100000
#define EE_EDGES 3200000
#define FDIM 256
#define CDIM 64
#define LN_EPS 1e-5

// ---------------- scratch (static device globals; no allocation) ----------------
__device__ int    g_deg_s[NN_NODES];
__device__ int    g_deg_d[NN_NODES];
__device__ float  g_norm_s[NN_NODES];
__device__ float  g_norm_d[NN_NODES];
__device__ int    g_row_off[NN_NODES + 1];
__device__ int    g_cursor[NN_NODES];
__device__ int    g_col[EE_EDGES];
__device__ __half g_x16[(size_t)NN_NODES * FDIM];   // fp16 input features
__device__ __half g_h16[(size_t)NN_NODES * FDIM];   // fp16 hidden (gather source + L3 A)
__device__ __half g_agg16[(size_t)NN_NODES * FDIM]; // fp16 aggregate (GEMM A)
__device__ __half g_t16[(size_t)NN_NODES * CDIM];   // fp16 layer-3 GEMM out
__device__ double g_stats[2];   // sum, sumsq
__device__ float  g_ln[2];      // mu, inv_std
__device__ float  g_csum[CDIM]; // column sums of W2 (layer-3 LN fold)
// pre-split, pre-transposed weights: [n][K] fp16 hi/lo
__device__ __half g_w0h[FDIM * FDIM], g_w0l[FDIM * FDIM];
__device__ __half g_w1h[FDIM * FDIM], g_w1l[FDIM * FDIM];
__device__ __half g_w2h[CDIM * FDIM], g_w2l[CDIM * FDIM];

// ---------------- setup kernels ----------------
__global__ void k_init() {
    int i = blockIdx.x * blockDim.x + threadIdx.x;
    if (i < NN_NODES) { g_deg_s[i] = 0; g_deg_d[i] = 0; }
    if (i == 0) { g_stats[0] = 0.0; g_stats[1] = 0.0; }
}

// ILP-4: int4 edge loads, 8 independent fire-and-forget atomics per thread
__global__ void k_degrees(const int* __restrict__ src, const int* __restrict__ dst) {
    int i = blockIdx.x * blockDim.x + threadIdx.x;
    if (i >= EE_EDGES / 4) return;
    int4 s = reinterpret_cast<const int4*>(src)[i];
    int4 d = reinterpret_cast<const int4*>(dst)[i];
    atomicAdd(&g_deg_s[s.x], 1);
    atomicAdd(&g_deg_s[s.y], 1);
    atomicAdd(&g_deg_s[s.z], 1);
    atomicAdd(&g_deg_s[s.w], 1);
    atomicAdd(&g_deg_d[d.x], 1);
    atomicAdd(&g_deg_d[d.y], 1);
    atomicAdd(&g_deg_d[d.z], 1);
    atomicAdd(&g_deg_d[d.w], 1);
}

__global__ void k_scan() {
    const int T = 1024;
    int t = threadIdx.x;
    const int chunk = (NN_NODES + T - 1) / T;
    int beg = t * chunk;
    int end = min(beg + chunk, NN_NODES);
    int local = 0;
    for (int i = beg; i < end; i++) local += g_deg_d[i];

    __shared__ int sh[T];
    sh[t] = local;
    __syncthreads();
    for (int off = 1; off < T; off <<= 1) {
        int v = (t >= off) ? sh[t - off] : 0;
        __syncthreads();
        sh[t] += v;
        __syncthreads();
    }
    int run = sh[t] - local;
    for (int i = beg; i < end; i++) {
        g_row_off[i] = run;
        g_cursor[i] = run;
        run += g_deg_d[i];
    }
    if (t == T - 1) g_row_off[NN_NODES] = sh[T - 1];

    for (int i = beg; i < end; i++) {
        g_norm_s[i] = rsqrtf((float)max(g_deg_s[i], 1));
        g_norm_d[i] = rsqrtf((float)max(g_deg_d[i], 1));
    }
}

// ILP-4: 4 independent atomic->store chains per thread
__global__ void k_fill(const int* __restrict__ src, const int* __restrict__ dst) {
    int i = blockIdx.x * blockDim.x + threadIdx.x;
    if (i >= EE_EDGES / 4) return;
    int4 s = reinterpret_cast<const int4*>(src)[i];
    int4 d = reinterpret_cast<const int4*>(dst)[i];
    int p0 = atomicAdd(&g_cursor[d.x], 1);
    int p1 = atomicAdd(&g_cursor[d.y], 1);
    int p2 = atomicAdd(&g_cursor[d.z], 1);
    int p3 = atomicAdd(&g_cursor[d.w], 1);
    g_col[p0] = s.x;
    g_col[p1] = s.y;
    g_col[p2] = s.z;
    g_col[p3] = s.w;
}

// fp32 -> fp16 convert (8 elements/thread)
__global__ void k_cvt(const float* __restrict__ x, __half* __restrict__ y, int n8) {
    int i = blockIdx.x * blockDim.x + threadIdx.x;
    if (i >= n8) return;
    float4 a = reinterpret_cast<const float4*>(x)[i * 2];
    float4 b = reinterpret_cast<const float4*>(x)[i * 2 + 1];
    __half2 h[4];
    h[0] = __floats2half2_rn(a.x, a.y);
    h[1] = __floats2half2_rn(a.z, a.w);
    h[2] = __floats2half2_rn(b.x, b.y);
    h[3] = __floats2half2_rn(b.z, b.w);
    reinterpret_cast<float4*>(y)[i] = *reinterpret_cast<float4*>(h);
}

// pre-split + transpose weights: W[K][N] fp32 -> Wh/Wl[N][K] fp16
__global__ void k_prep_w(const float* __restrict__ W, __half* __restrict__ Wh,
                         __half* __restrict__ Wl, int K, int N) {
    int idx = blockIdx.x * blockDim.x + threadIdx.x;
    if (idx >= K * N) return;
    int k = idx / N, n = idx % N;
    float x = W[idx];
    __half h = __float2half_rn(x);
    __half l = __float2half_rn(x - __half2float(h));
    Wh[n * K + k] = h;
    Wl[n * K + k] = l;
}

// column sums of W2 [FDIM][CDIM] for layer-3 LN fold
__global__ void k_csum(const float* __restrict__ W2) {
    int n = threadIdx.x;
    if (n >= CDIM) return;
    float s = 0.f;
    for (int k = 0; k < FDIM; k++) s += W2[k * CDIM + n];
    g_csum[n] = s;
}

// ---------------- SpMM: pull (warp per dst row), fp16 in/out, fp32 accum ----------------
template <bool LN>
__global__ void k_spmm256(const __half* __restrict__ hin, __half* __restrict__ out) {
    int gw = (blockIdx.x * blockDim.x + threadIdx.x) >> 5;
    int lane = threadIdx.x & 31;
    if (gw >= NN_NODES) return;

    float mu = 0.f, inv = 1.f;
    if (LN) { mu = g_ln[0]; inv = g_ln[1]; }

    int s0 = g_row_off[gw], s1 = g_row_off[gw + 1];
    float acc[8];
#pragma unroll
    for (int t = 0; t < 8; t++) acc[t] = 0.f;

    const float4* __restrict__ h4 = reinterpret_cast<const float4*>(hin); // 8 halves each

    for (int base = s0; base < s1; base += 32) {
        int kk = base + lane;
        int j = 0; float sc = 0.f;
        if (kk < s1) { j = g_col[kk]; sc = g_norm_s[j]; }
        int cnt = min(32, s1 - base);
#pragma unroll 8
        for (int i = 0; i < cnt; i++) {
            int   jj = __shfl_sync(0xffffffffu, j, i);
            float sj = __shfl_sync(0xffffffffu, sc, i);
            float4 raw = h4[(size_t)jj * 32 + lane];    // 8 halves
            const __half2* hp = reinterpret_cast<const __half2*>(&raw);
            float2 f0 = __half22float2(hp[0]);
            float2 f1 = __half22float2(hp[1]);
            float2 f2 = __half22float2(hp[2]);
            float2 f3 = __half22float2(hp[3]);
            float sv = LN ? (sj * inv) : sj;
            if (LN) {
                acc[0] = fmaf(f0.x - mu, sv, acc[0]); acc[1] = fmaf(f0.y - mu, sv, acc[1]);
                acc[2] = fmaf(f1.x - mu, sv, acc[2]); acc[3] = fmaf(f1.y - mu, sv, acc[3]);
                acc[4] = fmaf(f2.x - mu, sv, acc[4]); acc[5] = fmaf(f2.y - mu, sv, acc[5]);
                acc[6] = fmaf(f3.x - mu, sv, acc[6]); acc[7] = fmaf(f3.y - mu, sv, acc[7]);
            } else {
                acc[0] = fmaf(f0.x, sv, acc[0]); acc[1] = fmaf(f0.y, sv, acc[1]);
                acc[2] = fmaf(f1.x, sv, acc[2]); acc[3] = fmaf(f1.y, sv, acc[3]);
                acc[4] = fmaf(f2.x, sv, acc[4]); acc[5] = fmaf(f2.y, sv, acc[5]);
                acc[6] = fmaf(f3.x, sv, acc[6]); acc[7] = fmaf(f3.y, sv, acc[7]);
            }
        }
    }
    float nd = g_norm_d[gw];
    __half2 hv[4];
    hv[0] = __floats2half2_rn(acc[0] * nd, acc[1] * nd);
    hv[1] = __floats2half2_rn(acc[2] * nd, acc[3] * nd);
    hv[2] = __floats2half2_rn(acc[4] * nd, acc[5] * nd);
    hv[3] = __floats2half2_rn(acc[6] * nd, acc[7] * nd);
    reinterpret_cast<float4*>(out)[(size_t)gw * 32 + lane] = *reinterpret_cast<float4*>(hv);
}

// ---------------- SpMM 64-wide (final layer, fp16 gather, with bias) ----------------
__global__ void k_spmm64(const __half* __restrict__ tin, const float* __restrict__ bias,
                         float* __restrict__ out) {
    int gw = (blockIdx.x * blockDim.x + threadIdx.x) >> 5;
    int lane = threadIdx.x & 31;
    if (gw >= NN_NODES) return;

    int s0 = g_row_off[gw], s1 = g_row_off[gw + 1];
    float2 a = make_float2(0.f, 0.f);
    const __half2* __restrict__ t2 = reinterpret_cast<const __half2*>(tin);

    for (int base = s0; base < s1; base += 32) {
        int kk = base + lane;
        int j = 0; float sc = 0.f;
        if (kk < s1) { j = g_col[kk]; sc = g_norm_s[j]; }
        int cnt = min(32, s1 - base);
#pragma unroll 8
        for (int i = 0; i < cnt; i++) {
            int   jj = __shfl_sync(0xffffffffu, j, i);
            float sj = __shfl_sync(0xffffffffu, sc, i);
            float2 v = __half22float2(t2[(size_t)jj * (CDIM / 2) + lane]);
            a.x = fmaf(v.x, sj, a.x);
            a.y = fmaf(v.y, sj, a.y);
        }
    }
    float nd = g_norm_d[gw];
    float2 b = reinterpret_cast<const float2*>(bias)[lane];
    float2 o;
    o.x = fmaf(a.x, nd, b.x);
    o.y = fmaf(a.y, nd, b.y);
    reinterpret_cast<float2*>(out)[(size_t)gw * (CDIM / 2) + lane] = o;
}

// ---------------- fp16 tensor-core GEMM (R9: scalar frag loads, single buffer) ----------------
// C = A @ W, A fp16 (pure copy), W = Wh + Wl pre-split (exact).
// 2 MMAs per frag pair: Ah*Bh + Ah*Bl.
template <int BM, int BN, int WM, int WN, bool BIAS_RELU, bool STATS, bool LNFOLD,
          bool C_HALF>
__global__ void __launch_bounds__(256, 2)
k_gemm16(const __half* __restrict__ A16,
         const __half* __restrict__ Bh_g,   // [n][K] fp16 hi
         const __half* __restrict__ Bl_g,   // [n][K] fp16 lo
         const float* __restrict__ bias, void* __restrict__ Cp,
         int M, int Nn, int K) {
    constexpr int BK = 32;
    constexpr int LDA = BK + 8;          // halves; pitch 80B
    constexpr int LDB = BK + 8;
    constexpr int NWARP = (BM / WM) * (BN / WN);
    constexpr int NT = NWARP * 32;
    constexpr int MFRAG = WM / 16;
    constexpr int NFRAG = WN / 8;
    static_assert(BM * (BK / 16) == NT, "A staging map");

    __shared__ __half As[BM * LDA];
    __shared__ __half Bs_h[BN * LDB];
    __shared__ __half Bs_l[BN * LDB];

    const int tid  = threadIdx.x;
    const int lane = tid & 31;
    const int warp = tid >> 5;
    const int wm0 = (warp / (BN / WN)) * WM;
    const int wn0 = (warp % (BN / WN)) * WN;
    const int bm0 = blockIdx.x * BM;
    const int bn0 = blockIdx.y * BN;

    float acc[MFRAG][NFRAG][4];
#pragma unroll
    for (int i = 0; i < MFRAG; i++)
#pragma unroll
        for (int j = 0; j < NFRAG; j++)
#pragma unroll
            for (int q = 0; q < 4; q++) acc[i][j][q] = 0.f;

    const int gr = lane >> 2;
    const int gc = lane & 3;

    // A staging: 2 threads per row, 16 consecutive halves (32B) each — pure copy
    const int am = tid >> 1;
    const int aq = tid & 1;
    const int arow = bm0 + am;
    const bool aok = arow < M;

    for (int k0 = 0; k0 < K; k0 += BK) {
        // ---- stage A: float4 copies ----
        {
            uint4 v0 = make_uint4(0u, 0u, 0u, 0u), v1 = v0;
            if (aok) {
                const uint4* s = reinterpret_cast<const uint4*>(&A16[(size_t)arow * K + k0 + aq * 16]);
                v0 = s[0]; v1 = s[1];
            }
            uint4* pa = reinterpret_cast<uint4*>(&As[am * LDA + aq * 16]);
            pa[0] = v0; pa[1] = v1;
        }
        // ---- stage B: float4 copies from pre-split [n][K] fp16 ----
        constexpr int B4 = BN * BK / 8;   // float4 count
#pragma unroll
        for (int p = 0; p < B4 / NT; p++) {
            int idx = tid + p * NT;
            int n = idx / (BK / 8), seg = idx % (BK / 8);
            size_t goff = (size_t)(bn0 + n) * K + k0 + seg * 8;
            *reinterpret_cast<uint4*>(&Bs_h[n * LDB + seg * 8]) =
                *reinterpret_cast<const uint4*>(&Bh_g[goff]);
            *reinterpret_cast<uint4*>(&Bs_l[n * LDB + seg * 8]) =
                *reinterpret_cast<const uint4*>(&Bl_g[goff]);
        }
        __syncthreads();

#pragma unroll
        for (int ks = 0; ks < BK / 16; ks++) {
            const int kb = ks * 16;
            unsigned a[MFRAG][4];
#pragma unroll
            for (int mi = 0; mi < MFRAG; mi++) {
                int r = wm0 + mi * 16 + gr;
                a[mi][0] = *reinterpret_cast<const unsigned*>(&As[r * LDA + kb + 2 * gc]);
                a[mi][1] = *reinterpret_cast<const unsigned*>(&As[(r + 8) * LDA + kb + 2 * gc]);
                a[mi][2] = *reinterpret_cast<const unsigned*>(&As[r * LDA + kb + 2 * gc + 8]);
                a[mi][3] = *reinterpret_cast<const unsigned*>(&As[(r + 8) * LDA + kb + 2 * gc + 8]);
            }
            unsigned bh[NFRAG][2], bl[NFRAG][2];
#pragma unroll
            for (int ni = 0; ni < NFRAG; ni++) {
                int c = wn0 + ni * 8 + gr;
                bh[ni][0] = *reinterpret_cast<const unsigned*>(&Bs_h[c * LDB + kb + 2 * gc]);
                bh[ni][1] = *reinterpret_cast<const unsigned*>(&Bs_h[c * LDB + kb + 2 * gc + 8]);
                bl[ni][0] = *reinterpret_cast<const unsigned*>(&Bs_l[c * LDB + kb + 2 * gc]);
                bl[ni][1] = *reinterpret_cast<const unsigned*>(&Bs_l[c * LDB + kb + 2 * gc + 8]);
            }
#pragma unroll
            for (int mi = 0; mi < MFRAG; mi++)
#pragma unroll
                for (int ni = 0; ni < NFRAG; ni++) {
#define MMA_F16(B0,B1)                                                           \
    asm volatile("mma.sync.aligned.m16n8k16.row.col.f32.f16.f16.f32 "            \
                 "{%0,%1,%2,%3}, {%4,%5,%6,%7}, {%8,%9}, {%0,%1,%2,%3};"         \
                 : "+f"(acc[mi][ni][0]), "+f"(acc[mi][ni][1]),                   \
                   "+f"(acc[mi][ni][2]), "+f"(acc[mi][ni][3])                    \
                 : "r"(a[mi][0]), "r"(a[mi][1]), "r"(a[mi][2]), "r"(a[mi][3]),   \
                   "r"(B0), "r"(B1))
                    MMA_F16(bl[ni][0], bl[ni][1]);
                    MMA_F16(bh[ni][0], bh[ni][1]);
#undef MMA_F16
                }
        }
        __syncthreads();
    }

    // ---- epilogue ----
    float mu = 0.f, inv = 1.f;
    if (LNFOLD) { mu = g_ln[0]; inv = g_ln[1]; }
    double psum = 0.0, psq = 0.0;
#pragma unroll
    for (int mi = 0; mi < MFRAG; mi++) {
#pragma unroll
        for (int ni = 0; ni < NFRAG; ni++) {
            int c0 = bn0 + wn0 + ni * 8 + gc * 2;
            float2 bb = make_float2(0.f, 0.f);
            if (BIAS_RELU) bb = *reinterpret_cast<const float2*>(&bias[c0]);
            float2 cs = make_float2(0.f, 0.f);
            if (LNFOLD) cs = *reinterpret_cast<const float2*>(&g_csum[c0]);
#pragma unroll
            for (int hf = 0; hf < 2; hf++) {
                int row = bm0 + wm0 + mi * 16 + gr + hf * 8;
                if (row >= M) continue;
                float x = acc[mi][ni][hf * 2 + 0];
                float y = acc[mi][ni][hf * 2 + 1];
                if (BIAS_RELU) {
                    x = fmaxf(x + bb.x, 0.f);
                    y = fmaxf(y + bb.y, 0.f);
                }
                if (LNFOLD) {
                    x = x * inv - mu * inv * cs.x;
                    y = y * inv - mu * inv * cs.y;
                }
                if (C_HALF) {
                    __half* C16 = (__half*)Cp;
                    *reinterpret_cast<__half2*>(&C16[(size_t)row * Nn + c0]) =
                        __floats2half2_rn(x, y);
                } else {
                    float* Cf = (float*)Cp;
                    *reinterpret_cast<float2*>(&Cf[(size_t)row * Nn + c0]) = make_float2(x, y);
                }
                if (STATS) {
                    psum += (double)x + (double)y;
                    psq  += (double)x * x + (double)y * y;
                }
            }
        }
    }

    if (STATS) {
#pragma unroll
        for (int off = 16; off > 0; off >>= 1) {
            psum += __shfl_down_sync(0xffffffffu, psum, off);
            psq  += __shfl_down_sync(0xffffffffu, psq, off);
        }
        if (lane == 0) {
            atomicAdd(&g_stats[0], psum);
            atomicAdd(&g_stats[1], psq);
        }
    }
}

__global__ void k_finalize(double count) {
    double s = g_stats[0], ss = g_stats[1];
    double mu = s / count;
    double var = ss / count - mu * mu;
    g_ln[0] = (float)mu;
    g_ln[1] = (float)(1.0 / sqrt(var + (double)LN_EPS));
    g_stats[0] = 0.0;
    g_stats[1] = 0.0;
}

// ---------------- launch ----------------
extern "C" void kernel_launch(void* const* d_in, const int* in_sizes, int n_in,
                              void* d_out, int out_size) {
    const float* feat = (const float*)d_in[0];
    const int*   src  = (const int*)d_in[1];
    const int*   dst  = (const int*)d_in[2];
    const float* W0   = (const float*)d_in[3];
    const float* b0   = (const float*)d_in[4];
    const float* W1   = (const float*)d_in[5];
    const float* b1   = (const float*)d_in[6];
    const float* W2   = (const float*)d_in[7];
    const float* b2   = (const float*)d_in[8];
    float* out = (float*)d_out;

    __half *x16, *h16, *agg16, *tbuf;
    __half *w0h, *w0l, *w1h, *w1l, *w2h, *w2l;
    cudaGetSymbolAddress((void**)&x16, g_x16);
    cudaGetSymbolAddress((void**)&h16, g_h16);
    cudaGetSymbolAddress((void**)&agg16, g_agg16);
    cudaGetSymbolAddress((void**)&tbuf, g_t16);
    cudaGetSymbolAddress((void**)&w0h, g_w0h);
    cudaGetSymbolAddress((void**)&w0l, g_w0l);
    cudaGetSymbolAddress((void**)&w1h, g_w1h);
    cudaGetSymbolAddress((void**)&w1l, g_w1l);
    cudaGetSymbolAddress((void**)&w2h, g_w2h);
    cudaGetSymbolAddress((void**)&w2l, g_w2l);

    const int NB_N = (NN_NODES + 255) / 256;
    const int NB_E4 = ((EE_EDGES / 4) + 255) / 256;  // ILP-4 edge kernels
    const int NB_W = (NN_NODES * 32 + 255) / 256;    // warp per row
    const int NB_C = ((NN_NODES * FDIM / 8) + 255) / 256;

    // setup: degrees, norms, CSR (by dst), fp16 features, split weights
    k_init<<<NB_N, 256>>>();
    k_degrees<<<NB_E4, 256>>>(src, dst);
    k_scan<<<1, 1024>>>();
    k_fill<<<NB_E4, 256>>>(src, dst);
    k_cvt<<<NB_C, 256>>>(feat, x16, NN_NODES * FDIM / 8);
    k_prep_w<<<(FDIM * FDIM + 255) / 256, 256>>>(W0, w0h, w0l, FDIM, FDIM);
    k_prep_w<<<(FDIM * FDIM + 255) / 256, 256>>>(W1, w1h, w1l, FDIM, FDIM);
    k_prep_w<<<(FDIM * CDIM + 255) / 256, 256>>>(W2, w2h, w2l, FDIM, CDIM);
    k_csum<<<1, CDIM>>>(W2);

    const int GM = (NN_NODES + 127) / 128;
    const double cnt = (double)NN_NODES * FDIM;

    // layer 1: agg16 = fp16(DAD*X) ; h1 = relu(agg@W0 + b0) (+stats), fp16
    k_spmm256<false><<<NB_W, 256>>>(x16, agg16);
    k_gemm16<128, 128, 64, 32, true, true, false, true>
        <<<dim3(GM, FDIM / 128), 256>>>(agg16, w0h, w0l, b0, h16, NN_NODES, FDIM, FDIM);
    k_finalize<<<1, 1>>>(cnt);

    // layer 2: agg16 = fp16(DAD*LN(h1)) ; h2 = relu(agg@W1 + b1) (+stats), fp16
    k_spmm256<true><<<NB_W, 256>>>(h16, agg16);
    k_gemm16<128, 128, 64, 32, true, true, false, true>
        <<<dim3(GM, FDIM / 128), 256>>>(agg16, w1h, w1l, b1, h16, NN_NODES, FDIM, FDIM);
    k_finalize<<<1, 1>>>(cnt);

    // layer 3: t16 = fp16(LN(h2)@W2) via epilogue fold ; out = DAD*t + b2
    k_gemm16<128, 64, 64, 16, false, false, true, true>
        <<<dim3(GM, 1), 256>>>(h16, w2h, w2l, nullptr, tbuf, NN_NODES, CDIM, FDIM);
    k_spmm64<<<NB_W, 256>>>(tbuf, b2, out);
}

// round 14
// speedup vs baseline: 1.2914x; 1.0194x over previous
#include <cuda_runtime.h>
#include <cuda_fp16.h>
#include <math.h>
#include <stdint.h>

#define NN_NODES 100000
#define EE_EDGES 3200000
#define FDIM 256
#define CDIM 64
#define LN_EPS 1e-5

// ---------------- scratch (static device globals; no allocation) ----------------
__device__ int    g_deg_s[NN_NODES];
__device__ int    g_deg_d[NN_NODES];
__device__ float  g_norm_s[NN_NODES];
__device__ float  g_norm_d[NN_NODES];
__device__ int    g_row_off[NN_NODES + 1];
__device__ int    g_cursor[NN_NODES];
__device__ int2   g_edge[EE_EDGES];                 // {src, norm_s bits} per edge (dst-CSR)
__device__ __half g_x16[(size_t)NN_NODES * FDIM];   // fp16 input features
__device__ __half g_h16[(size_t)NN_NODES * FDIM];   // fp16 hidden (gather source + L3 A)
__device__ __half g_agg16[(size_t)NN_NODES * FDIM]; // fp16 aggregate (GEMM A)
__device__ __half g_t16[(size_t)NN_NODES * CDIM];   // fp16 layer-3 GEMM out
__device__ double g_stats[2];   // sum, sumsq
__device__ float  g_ln[2];      // mu, inv_std
__device__ float  g_csum[CDIM]; // column sums of W2 (layer-3 LN fold)
// pre-transposed weights: [n][K] fp16 (single-rounded)
__device__ __half g_w0h[FDIM * FDIM];
__device__ __half g_w1h[FDIM * FDIM];
__device__ __half g_w2h[CDIM * FDIM];

// ---------------- setup kernels ----------------
__global__ void k_init() {
    int i = blockIdx.x * blockDim.x + threadIdx.x;
    if (i < NN_NODES) { g_deg_s[i] = 0; g_deg_d[i] = 0; }
    if (i == 0) { g_stats[0] = 0.0; g_stats[1] = 0.0; }
}

__global__ void k_degrees(const int* __restrict__ src, const int* __restrict__ dst) {
    int i = blockIdx.x * blockDim.x + threadIdx.x;
    if (i >= EE_EDGES / 4) return;
    int4 s = reinterpret_cast<const int4*>(src)[i];
    int4 d = reinterpret_cast<const int4*>(dst)[i];
    atomicAdd(&g_deg_s[s.x], 1);
    atomicAdd(&g_deg_s[s.y], 1);
    atomicAdd(&g_deg_s[s.z], 1);
    atomicAdd(&g_deg_s[s.w], 1);
    atomicAdd(&g_deg_d[d.x], 1);
    atomicAdd(&g_deg_d[d.y], 1);
    atomicAdd(&g_deg_d[d.z], 1);
    atomicAdd(&g_deg_d[d.w], 1);
}

__global__ void k_scan() {
    const int T = 1024;
    int t = threadIdx.x;
    const int chunk = (NN_NODES + T - 1) / T;
    int beg = t * chunk;
    int end = min(beg + chunk, NN_NODES);
    int local = 0;
    for (int i = beg; i < end; i++) local += g_deg_d[i];

    __shared__ int sh[T];
    sh[t] = local;
    __syncthreads();
    for (int off = 1; off < T; off <<= 1) {
        int v = (t >= off) ? sh[t - off] : 0;
        __syncthreads();
        sh[t] += v;
        __syncthreads();
    }
    int run = sh[t] - local;
    for (int i = beg; i < end; i++) {
        g_row_off[i] = run;
        g_cursor[i] = run;
        run += g_deg_d[i];
    }
    if (t == T - 1) g_row_off[NN_NODES] = sh[T - 1];

    for (int i = beg; i < end; i++) {
        g_norm_s[i] = rsqrtf((float)max(g_deg_s[i], 1));
        g_norm_d[i] = rsqrtf((float)max(g_deg_d[i], 1));
    }
}

// fill CSR with packed (src, norm_s) payload (norms ready after k_scan)
__global__ void k_fill(const int* __restrict__ src, const int* __restrict__ dst) {
    int i = blockIdx.x * blockDim.x + threadIdx.x;
    if (i >= EE_EDGES / 4) return;
    int4 s = reinterpret_cast<const int4*>(src)[i];
    int4 d = reinterpret_cast<const int4*>(dst)[i];
    int p0 = atomicAdd(&g_cursor[d.x], 1);
    int p1 = atomicAdd(&g_cursor[d.y], 1);
    int p2 = atomicAdd(&g_cursor[d.z], 1);
    int p3 = atomicAdd(&g_cursor[d.w], 1);
    g_edge[p0] = make_int2(s.x, __float_as_int(g_norm_s[s.x]));
    g_edge[p1] = make_int2(s.y, __float_as_int(g_norm_s[s.y]));
    g_edge[p2] = make_int2(s.z, __float_as_int(g_norm_s[s.z]));
    g_edge[p3] = make_int2(s.w, __float_as_int(g_norm_s[s.w]));
}

// fp32 -> fp16 convert (8 elements/thread)
__global__ void k_cvt(const float* __restrict__ x, __half* __restrict__ y, int n8) {
    int i = blockIdx.x * blockDim.x + threadIdx.x;
    if (i >= n8) return;
    float4 a = reinterpret_cast<const float4*>(x)[i * 2];
    float4 b = reinterpret_cast<const float4*>(x)[i * 2 + 1];
    __half2 h[4];
    h[0] = __floats2half2_rn(a.x, a.y);
    h[1] = __floats2half2_rn(a.z, a.w);
    h[2] = __floats2half2_rn(b.x, b.y);
    h[3] = __floats2half2_rn(b.z, b.w);
    reinterpret_cast<float4*>(y)[i] = *reinterpret_cast<float4*>(h);
}

// transpose weights: W[K][N] fp32 -> Wh[N][K] fp16 (single rounding)
__global__ void k_prep_w(const float* __restrict__ W, __half* __restrict__ Wh,
                         int K, int N) {
    int idx = blockIdx.x * blockDim.x + threadIdx.x;
    if (idx >= K * N) return;
    int k = idx / N, n = idx % N;
    Wh[n * K + k] = __float2half_rn(W[idx]);
}

// column sums of W2 [FDIM][CDIM] for layer-3 LN fold
__global__ void k_csum(const float* __restrict__ W2) {
    int n = threadIdx.x;
    if (n >= CDIM) return;
    float s = 0.f;
    for (int k = 0; k < FDIM; k++) s += W2[k * CDIM + n];
    g_csum[n] = s;
}

// ---------------- SpMM: pull (warp per dst row), fp16 in/out, fp32 accum ----------------
template <bool LN>
__global__ void k_spmm256(const __half* __restrict__ hin, __half* __restrict__ out) {
    int gw = (blockIdx.x * blockDim.x + threadIdx.x) >> 5;
    int lane = threadIdx.x & 31;
    if (gw >= NN_NODES) return;

    float mu = 0.f, inv = 1.f;
    if (LN) { mu = g_ln[0]; inv = g_ln[1]; }

    int s0 = g_row_off[gw], s1 = g_row_off[gw + 1];
    float acc[8];
#pragma unroll
    for (int t = 0; t < 8; t++) acc[t] = 0.f;

    const float4* __restrict__ h4 = reinterpret_cast<const float4*>(hin); // 8 halves each

    for (int base = s0; base < s1; base += 32) {
        int kk = base + lane;
        int j = 0; float sc = 0.f;
        if (kk < s1) {
            int2 e = g_edge[kk];
            j = e.x; sc = __int_as_float(e.y);
        }
        int cnt = min(32, s1 - base);
#pragma unroll 8
        for (int i = 0; i < cnt; i++) {
            int   jj = __shfl_sync(0xffffffffu, j, i);
            float sj = __shfl_sync(0xffffffffu, sc, i);
            float4 raw = h4[(size_t)jj * 32 + lane];    // 8 halves
            const __half2* hp = reinterpret_cast<const __half2*>(&raw);
            float2 f0 = __half22float2(hp[0]);
            float2 f1 = __half22float2(hp[1]);
            float2 f2 = __half22float2(hp[2]);
            float2 f3 = __half22float2(hp[3]);
            float sv = LN ? (sj * inv) : sj;
            if (LN) {
                acc[0] = fmaf(f0.x - mu, sv, acc[0]); acc[1] = fmaf(f0.y - mu, sv, acc[1]);
                acc[2] = fmaf(f1.x - mu, sv, acc[2]); acc[3] = fmaf(f1.y - mu, sv, acc[3]);
                acc[4] = fmaf(f2.x - mu, sv, acc[4]); acc[5] = fmaf(f2.y - mu, sv, acc[5]);
                acc[6] = fmaf(f3.x - mu, sv, acc[6]); acc[7] = fmaf(f3.y - mu, sv, acc[7]);
            } else {
                acc[0] = fmaf(f0.x, sv, acc[0]); acc[1] = fmaf(f0.y, sv, acc[1]);
                acc[2] = fmaf(f1.x, sv, acc[2]); acc[3] = fmaf(f1.y, sv, acc[3]);
                acc[4] = fmaf(f2.x, sv, acc[4]); acc[5] = fmaf(f2.y, sv, acc[5]);
                acc[6] = fmaf(f3.x, sv, acc[6]); acc[7] = fmaf(f3.y, sv, acc[7]);
            }
        }
    }
    float nd = g_norm_d[gw];
    __half2 hv[4];
    hv[0] = __floats2half2_rn(acc[0] * nd, acc[1] * nd);
    hv[1] = __floats2half2_rn(acc[2] * nd, acc[3] * nd);
    hv[2] = __floats2half2_rn(acc[4] * nd, acc[5] * nd);
    hv[3] = __floats2half2_rn(acc[6] * nd, acc[7] * nd);
    reinterpret_cast<float4*>(out)[(size_t)gw * 32 + lane] = *reinterpret_cast<float4*>(hv);
}

// ---------------- SpMM 64-wide (final layer, fp16 gather, with bias) ----------------
__global__ void k_spmm64(const __half* __restrict__ tin, const float* __restrict__ bias,
                         float* __restrict__ out) {
    int gw = (blockIdx.x * blockDim.x + threadIdx.x) >> 5;
    int lane = threadIdx.x & 31;
    if (gw >= NN_NODES) return;

    int s0 = g_row_off[gw], s1 = g_row_off[gw + 1];
    float2 a = make_float2(0.f, 0.f);
    const __half2* __restrict__ t2 = reinterpret_cast<const __half2*>(tin);

    for (int base = s0; base < s1; base += 32) {
        int kk = base + lane;
        int j = 0; float sc = 0.f;
        if (kk < s1) {
            int2 e = g_edge[kk];
            j = e.x; sc = __int_as_float(e.y);
        }
        int cnt = min(32, s1 - base);
#pragma unroll 8
        for (int i = 0; i < cnt; i++) {
            int   jj = __shfl_sync(0xffffffffu, j, i);
            float sj = __shfl_sync(0xffffffffu, sc, i);
            float2 v = __half22float2(t2[(size_t)jj * (CDIM / 2) + lane]);
            a.x = fmaf(v.x, sj, a.x);
            a.y = fmaf(v.y, sj, a.y);
        }
    }
    float nd = g_norm_d[gw];
    float2 b = reinterpret_cast<const float2*>(bias)[lane];
    float2 o;
    o.x = fmaf(a.x, nd, b.x);
    o.y = fmaf(a.y, nd, b.y);
    reinterpret_cast<float2*>(out)[(size_t)gw * (CDIM / 2) + lane] = o;
}

// ---------------- fp16 tensor-core GEMM (single MMA per frag pair) ----------------
// C = A @ W, A fp16 (pure copy), W fp16 single-rounded.
template <int BM, int BN, int WM, int WN, bool BIAS_RELU, bool STATS, bool LNFOLD,
          bool C_HALF>
__global__ void __launch_bounds__(256, 2)
k_gemm16(const __half* __restrict__ A16,
         const __half* __restrict__ Bh_g,   // [n][K] fp16
         const float* __restrict__ bias, void* __restrict__ Cp,
         int M, int Nn, int K) {
    constexpr int BK = 32;
    constexpr int LDA = BK + 8;          // halves; pitch 80B
    constexpr int LDB = BK + 8;
    constexpr int NWARP = (BM / WM) * (BN / WN);
    constexpr int NT = NWARP * 32;
    constexpr int MFRAG = WM / 16;
    constexpr int NFRAG = WN / 8;
    static_assert(BM * (BK / 16) == NT, "A staging map");

    __shared__ __half As[BM * LDA];
    __shared__ __half Bs_h[BN * LDB];

    const int tid  = threadIdx.x;
    const int lane = tid & 31;
    const int warp = tid >> 5;
    const int wm0 = (warp / (BN / WN)) * WM;
    const int wn0 = (warp % (BN / WN)) * WN;
    const int bm0 = blockIdx.x * BM;
    const int bn0 = blockIdx.y * BN;

    float acc[MFRAG][NFRAG][4];
#pragma unroll
    for (int i = 0; i < MFRAG; i++)
#pragma unroll
        for (int j = 0; j < NFRAG; j++)
#pragma unroll
            for (int q = 0; q < 4; q++) acc[i][j][q] = 0.f;

    const int gr = lane >> 2;
    const int gc = lane & 3;

    // A staging: 2 threads per row, 16 consecutive halves (32B) each — pure copy
    const int am = tid >> 1;
    const int aq = tid & 1;
    const int arow = bm0 + am;
    const bool aok = arow < M;

    for (int k0 = 0; k0 < K; k0 += BK) {
        // ---- stage A: float4 copies ----
        {
            uint4 v0 = make_uint4(0u, 0u, 0u, 0u), v1 = v0;
            if (aok) {
                const uint4* s = reinterpret_cast<const uint4*>(&A16[(size_t)arow * K + k0 + aq * 16]);
                v0 = s[0]; v1 = s[1];
            }
            uint4* pa = reinterpret_cast<uint4*>(&As[am * LDA + aq * 16]);
            pa[0] = v0; pa[1] = v1;
        }
        // ---- stage B: float4 copies from pre-transposed [n][K] fp16 ----
        constexpr int B4 = BN * BK / 8;   // float4 count
#pragma unroll
        for (int p = 0; p < B4 / NT; p++) {
            int idx = tid + p * NT;
            int n = idx / (BK / 8), seg = idx % (BK / 8);
            size_t goff = (size_t)(bn0 + n) * K + k0 + seg * 8;
            *reinterpret_cast<uint4*>(&Bs_h[n * LDB + seg * 8]) =
                *reinterpret_cast<const uint4*>(&Bh_g[goff]);
        }
        __syncthreads();

#pragma unroll
        for (int ks = 0; ks < BK / 16; ks++) {
            const int kb = ks * 16;
            unsigned a[MFRAG][4];
#pragma unroll
            for (int mi = 0; mi < MFRAG; mi++) {
                int r = wm0 + mi * 16 + gr;
                a[mi][0] = *reinterpret_cast<const unsigned*>(&As[r * LDA + kb + 2 * gc]);
                a[mi][1] = *reinterpret_cast<const unsigned*>(&As[(r + 8) * LDA + kb + 2 * gc]);
                a[mi][2] = *reinterpret_cast<const unsigned*>(&As[r * LDA + kb + 2 * gc + 8]);
                a[mi][3] = *reinterpret_cast<const unsigned*>(&As[(r + 8) * LDA + kb + 2 * gc + 8]);
            }
            unsigned bh[NFRAG][2];
#pragma unroll
            for (int ni = 0; ni < NFRAG; ni++) {
                int c = wn0 + ni * 8 + gr;
                bh[ni][0] = *reinterpret_cast<const unsigned*>(&Bs_h[c * LDB + kb + 2 * gc]);
                bh[ni][1] = *reinterpret_cast<const unsigned*>(&Bs_h[c * LDB + kb + 2 * gc + 8]);
            }
#pragma unroll
            for (int mi = 0; mi < MFRAG; mi++)
#pragma unroll
                for (int ni = 0; ni < NFRAG; ni++) {
                    asm volatile("mma.sync.aligned.m16n8k16.row.col.f32.f16.f16.f32 "
                                 "{%0,%1,%2,%3}, {%4,%5,%6,%7}, {%8,%9}, {%0,%1,%2,%3};"
                                 : "+f"(acc[mi][ni][0]), "+f"(acc[mi][ni][1]),
                                   "+f"(acc[mi][ni][2]), "+f"(acc[mi][ni][3])
                                 : "r"(a[mi][0]), "r"(a[mi][1]), "r"(a[mi][2]), "r"(a[mi][3]),
                                   "r"(bh[ni][0]), "r"(bh[ni][1]));
                }
        }
        __syncthreads();
    }

    // ---- epilogue ----
    float mu = 0.f, inv = 1.f;
    if (LNFOLD) { mu = g_ln[0]; inv = g_ln[1]; }
    double psum = 0.0, psq = 0.0;
#pragma unroll
    for (int mi = 0; mi < MFRAG; mi++) {
#pragma unroll
        for (int ni = 0; ni < NFRAG; ni++) {
            int c0 = bn0 + wn0 + ni * 8 + gc * 2;
            float2 bb = make_float2(0.f, 0.f);
            if (BIAS_RELU) bb = *reinterpret_cast<const float2*>(&bias[c0]);
            float2 cs = make_float2(0.f, 0.f);
            if (LNFOLD) cs = *reinterpret_cast<const float2*>(&g_csum[c0]);
#pragma unroll
            for (int hf = 0; hf < 2; hf++) {
                int row = bm0 + wm0 + mi * 16 + gr + hf * 8;
                if (row >= M) continue;
                float x = acc[mi][ni][hf * 2 + 0];
                float y = acc[mi][ni][hf * 2 + 1];
                if (BIAS_RELU) {
                    x = fmaxf(x + bb.x, 0.f);
                    y = fmaxf(y + bb.y, 0.f);
                }
                if (LNFOLD) {
                    x = x * inv - mu * inv * cs.x;
                    y = y * inv - mu * inv * cs.y;
                }
                if (C_HALF) {
                    __half* C16 = (__half*)Cp;
                    *reinterpret_cast<__half2*>(&C16[(size_t)row * Nn + c0]) =
                        __floats2half2_rn(x, y);
                } else {
                    float* Cf = (float*)Cp;
                    *reinterpret_cast<float2*>(&Cf[(size_t)row * Nn + c0]) = make_float2(x, y);
                }
                if (STATS) {
                    psum += (double)x + (double)y;
                    psq  += (double)x * x + (double)y * y;
                }
            }
        }
    }

    if (STATS) {
#pragma unroll
        for (int off = 16; off > 0; off >>= 1) {
            psum += __shfl_down_sync(0xffffffffu, psum, off);
            psq  += __shfl_down_sync(0xffffffffu, psq, off);
        }
        if (lane == 0) {
            atomicAdd(&g_stats[0], psum);
            atomicAdd(&g_stats[1], psq);
        }
    }
}

__global__ void k_finalize(double count) {
    double s = g_stats[0], ss = g_stats[1];
    double mu = s / count;
    double var = ss / count - mu * mu;
    g_ln[0] = (float)mu;
    g_ln[1] = (float)(1.0 / sqrt(var + (double)LN_EPS));
    g_stats[0] = 0.0;
    g_stats[1] = 0.0;
}

// ---------------- launch ----------------
extern "C" void kernel_launch(void* const* d_in, const int* in_sizes, int n_in,
                              void* d_out, int out_size) {
    const float* feat = (const float*)d_in[0];
    const int*   src  = (const int*)d_in[1];
    const int*   dst  = (const int*)d_in[2];
    const float* W0   = (const float*)d_in[3];
    const float* b0   = (const float*)d_in[4];
    const float* W1   = (const float*)d_in[5];
    const float* b1   = (const float*)d_in[6];
    const float* W2   = (const float*)d_in[7];
    const float* b2   = (const float*)d_in[8];
    float* out = (float*)d_out;

    __half *x16, *h16, *agg16, *tbuf;
    __half *w0h, *w1h, *w2h;
    cudaGetSymbolAddress((void**)&x16, g_x16);
    cudaGetSymbolAddress((void**)&h16, g_h16);
    cudaGetSymbolAddress((void**)&agg16, g_agg16);
    cudaGetSymbolAddress((void**)&tbuf, g_t16);
    cudaGetSymbolAddress((void**)&w0h, g_w0h);
    cudaGetSymbolAddress((void**)&w1h, g_w1h);
    cudaGetSymbolAddress((void**)&w2h, g_w2h);

    const int NB_N = (NN_NODES + 255) / 256;
    const int NB_E4 = ((EE_EDGES / 4) + 255) / 256;  // ILP-4 edge kernels
    const int NB_W = (NN_NODES * 32 + 255) / 256;    // warp per row
    const int NB_C = ((NN_NODES * FDIM / 8) + 255) / 256;

    // setup: degrees, norms, CSR with packed payload, fp16 features, fp16 weights
    k_init<<<NB_N, 256>>>();
    k_degrees<<<NB_E4, 256>>>(src, dst);
    k_scan<<<1, 1024>>>();
    k_fill<<<NB_E4, 256>>>(src, dst);
    k_cvt<<<NB_C, 256>>>(feat, x16, NN_NODES * FDIM / 8);
    k_prep_w<<<(FDIM * FDIM + 255) / 256, 256>>>(W0, w0h, FDIM, FDIM);
    k_prep_w<<<(FDIM * FDIM + 255) / 256, 256>>>(W1, w1h, FDIM, FDIM);
    k_prep_w<<<(FDIM * CDIM + 255) / 256, 256>>>(W2, w2h, FDIM, CDIM);
    k_csum<<<1, CDIM>>>(W2);

    const int GM = (NN_NODES + 127) / 128;
    const double cnt = (double)NN_NODES * FDIM;

    // layer 1: agg16 = fp16(DAD*X) ; h1 = relu(agg@W0 + b0) (+stats), fp16
    k_spmm256<false><<<NB_W, 256>>>(x16, agg16);
    k_gemm16<128, 128, 64, 32, true, true, false, true>
        <<<dim3(GM, FDIM / 128), 256>>>(agg16, w0h, b0, h16, NN_NODES, FDIM, FDIM);
    k_finalize<<<1, 1>>>(cnt);

    // layer 2: agg16 = fp16(DAD*LN(h1)) ; h2 = relu(agg@W1 + b1) (+stats), fp16
    k_spmm256<true><<<NB_W, 256>>>(h16, agg16);
    k_gemm16<128, 128, 64, 32, true, true, false, true>
        <<<dim3(GM, FDIM / 128), 256>>>(agg16, w1h, b1, h16, NN_NODES, FDIM, FDIM);
    k_finalize<<<1, 1>>>(cnt);

    // layer 3: t16 = fp16(LN(h2)@W2) via epilogue fold ; out = DAD*t + b2
    k_gemm16<128, 64, 64, 16, false, false, true, true>
        <<<dim3(GM, 1), 256>>>(h16, w2h, nullptr, tbuf, NN_NODES, CDIM, FDIM);
    k_spmm64<<<NB_W, 256>>>(tbuf, b2, out);
}

// round 15
// speedup vs baseline: 1.7136x; 1.3270x over previous
#include <cuda_runtime.h>
#include <cuda_fp16.h>
#include <math.h>
#include <stdint.h>

#define NN_NODES 100000
#define EE_EDGES 3200000
#define FDIM 256
#define CDIM 64
#define LN_EPS 1e-5
#define TILE 256
#define NTILES ((NN_NODES + TILE - 1) / TILE)   // 391

// ---------------- scratch (static device globals; no allocation) ----------------
__device__ int    g_deg_s[NN_NODES];
__device__ int    g_deg_d[NN_NODES];
__device__ float  g_norm_s[NN_NODES];
__device__ float  g_norm_d[NN_NODES];
__device__ int    g_row_off[NN_NODES + 1];
__device__ int    g_cursor[NN_NODES];
__device__ int    g_part[NTILES];
__device__ int    g_toff[NTILES];
__device__ int2   g_edge[EE_EDGES];                 // {src, norm_s bits} per edge (dst-CSR)
__device__ __half g_x16[(size_t)NN_NODES * FDIM];   // fp16 input features
__device__ __half g_h16[(size_t)NN_NODES * FDIM];   // fp16 hidden (gather source + L3 A)
__device__ __half g_agg16[(size_t)NN_NODES * FDIM]; // fp16 aggregate (GEMM A)
__device__ __half g_t16[(size_t)NN_NODES * CDIM];   // fp16 layer-3 GEMM out
__device__ double g_stats[2];   // sum, sumsq
__device__ float  g_ln[2];      // mu, inv_std
__device__ float  g_csum[CDIM]; // column sums of W2 (layer-3 LN fold)
// pre-split, pre-transposed weights: [n][K] fp16 hi/lo (B exact)
__device__ __half g_w0h[FDIM * FDIM], g_w0l[FDIM * FDIM];
__device__ __half g_w1h[FDIM * FDIM], g_w1l[FDIM * FDIM];
__device__ __half g_w2h[CDIM * FDIM], g_w2l[CDIM * FDIM];

// ---------------- setup kernels ----------------
__global__ void k_init() {
    int i = blockIdx.x * blockDim.x + threadIdx.x;
    if (i < NN_NODES) { g_deg_s[i] = 0; g_deg_d[i] = 0; }
    if (i == 0) { g_stats[0] = 0.0; g_stats[1] = 0.0; }
}

__global__ void k_degrees(const int* __restrict__ src, const int* __restrict__ dst) {
    int i = blockIdx.x * blockDim.x + threadIdx.x;
    if (i >= EE_EDGES / 4) return;
    int4 s = reinterpret_cast<const int4*>(src)[i];
    int4 d = reinterpret_cast<const int4*>(dst)[i];
    atomicAdd(&g_deg_s[s.x], 1);
    atomicAdd(&g_deg_s[s.y], 1);
    atomicAdd(&g_deg_s[s.z], 1);
    atomicAdd(&g_deg_s[s.w], 1);
    atomicAdd(&g_deg_d[d.x], 1);
    atomicAdd(&g_deg_d[d.y], 1);
    atomicAdd(&g_deg_d[d.z], 1);
    atomicAdd(&g_deg_d[d.w], 1);
}

// multi-block scan: tile partial sums
__global__ void k_scan1() {
    __shared__ int sh[TILE];
    int t = threadIdx.x, b = blockIdx.x;
    int i = b * TILE + t;
    sh[t] = (i < NN_NODES) ? g_deg_d[i] : 0;
    __syncthreads();
#pragma unroll
    for (int off = TILE / 2; off > 0; off >>= 1) {
        if (t < off) sh[t] += sh[t + off];
        __syncthreads();
    }
    if (t == 0) g_part[b] = sh[0];
}

// scan of the 391 tile partials (1 block, 512 threads)
__global__ void k_scan2() {
    __shared__ int sh[512];
    int t = threadIdx.x;
    int v = (t < NTILES) ? g_part[t] : 0;
    sh[t] = v;
    __syncthreads();
    for (int off = 1; off < 512; off <<= 1) {
        int u = (t >= off) ? sh[t - off] : 0;
        __syncthreads();
        sh[t] += u;
        __syncthreads();
    }
    if (t < NTILES) g_toff[t] = sh[t] - v;   // exclusive
}

// per-tile exclusive scan + row_off/cursor/norms
__global__ void k_scan3() {
    __shared__ int sh[TILE];
    int t = threadIdx.x, b = blockIdx.x;
    int i = b * TILE + t;
    int d = (i < NN_NODES) ? g_deg_d[i] : 0;
    sh[t] = d;
    __syncthreads();
    for (int off = 1; off < TILE; off <<= 1) {
        int u = (t >= off) ? sh[t - off] : 0;
        __syncthreads();
        sh[t] += u;
        __syncthreads();
    }
    int excl = sh[t] - d + g_toff[b];
    if (i < NN_NODES) {
        g_row_off[i] = excl;
        g_cursor[i] = excl;
        g_norm_s[i] = rsqrtf((float)max(g_deg_s[i], 1));
        g_norm_d[i] = rsqrtf((float)max(g_deg_d[i], 1));
        if (i == NN_NODES - 1) g_row_off[NN_NODES] = excl + d;
    }
}

// fill CSR with packed (src, norm_s) payload (norms ready after scan)
__global__ void k_fill(const int* __restrict__ src, const int* __restrict__ dst) {
    int i = blockIdx.x * blockDim.x + threadIdx.x;
    if (i >= EE_EDGES / 4) return;
    int4 s = reinterpret_cast<const int4*>(src)[i];
    int4 d = reinterpret_cast<const int4*>(dst)[i];
    int p0 = atomicAdd(&g_cursor[d.x], 1);
    int p1 = atomicAdd(&g_cursor[d.y], 1);
    int p2 = atomicAdd(&g_cursor[d.z], 1);
    int p3 = atomicAdd(&g_cursor[d.w], 1);
    g_edge[p0] = make_int2(s.x, __float_as_int(g_norm_s[s.x]));
    g_edge[p1] = make_int2(s.y, __float_as_int(g_norm_s[s.y]));
    g_edge[p2] = make_int2(s.z, __float_as_int(g_norm_s[s.z]));
    g_edge[p3] = make_int2(s.w, __float_as_int(g_norm_s[s.w]));
}

// fp32 -> fp16 convert (8 elements/thread)
__global__ void k_cvt(const float* __restrict__ x, __half* __restrict__ y, int n8) {
    int i = blockIdx.x * blockDim.x + threadIdx.x;
    if (i >= n8) return;
    float4 a = reinterpret_cast<const float4*>(x)[i * 2];
    float4 b = reinterpret_cast<const float4*>(x)[i * 2 + 1];
    __half2 h[4];
    h[0] = __floats2half2_rn(a.x, a.y);
    h[1] = __floats2half2_rn(a.z, a.w);
    h[2] = __floats2half2_rn(b.x, b.y);
    h[3] = __floats2half2_rn(b.z, b.w);
    reinterpret_cast<float4*>(y)[i] = *reinterpret_cast<float4*>(h);
}

// pre-split + transpose weights: W[K][N] fp32 -> Wh/Wl[N][K] fp16 (B exact)
__global__ void k_prep_w(const float* __restrict__ W, __half* __restrict__ Wh,
                         __half* __restrict__ Wl, int K, int N) {
    int idx = blockIdx.x * blockDim.x + threadIdx.x;
    if (idx >= K * N) return;
    int k = idx / N, n = idx % N;
    float x = W[idx];
    __half h = __float2half_rn(x);
    __half l = __float2half_rn(x - __half2float(h));
    Wh[n * K + k] = h;
    Wl[n * K + k] = l;
}

// column sums of W2 [FDIM][CDIM], one block per column
__global__ void k_csum(const float* __restrict__ W2) {
    __shared__ float sh[FDIM];
    int n = blockIdx.x;
    int k = threadIdx.x;
    sh[k] = W2[k * CDIM + n];
    __syncthreads();
#pragma unroll
    for (int off = FDIM / 2; off > 0; off >>= 1) {
        if (k < off) sh[k] += sh[k + off];
        __syncthreads();
    }
    if (k == 0) g_csum[n] = sh[0];
}

// ---------------- SpMM: pull (warp per dst row), fp16 in/out, fp32 accum ----------------
template <bool LN>
__global__ void k_spmm256(const __half* __restrict__ hin, __half* __restrict__ out) {
    int gw = (blockIdx.x * blockDim.x + threadIdx.x) >> 5;
    int lane = threadIdx.x & 31;
    if (gw >= NN_NODES) return;

    float mu = 0.f, inv = 1.f;
    if (LN) { mu = g_ln[0]; inv = g_ln[1]; }

    int s0 = g_row_off[gw], s1 = g_row_off[gw + 1];
    float acc[8];
#pragma unroll
    for (int t = 0; t < 8; t++) acc[t] = 0.f;

    const float4* __restrict__ h4 = reinterpret_cast<const float4*>(hin); // 8 halves each

    for (int base = s0; base < s1; base += 32) {
        int kk = base + lane;
        int j = 0; float sc = 0.f;
        if (kk < s1) {
            int2 e = g_edge[kk];
            j = e.x; sc = __int_as_float(e.y);
        }
        int cnt = min(32, s1 - base);
#pragma unroll 8
        for (int i = 0; i < cnt; i++) {
            int   jj = __shfl_sync(0xffffffffu, j, i);
            float sj = __shfl_sync(0xffffffffu, sc, i);
            float4 raw = h4[(size_t)jj * 32 + lane];    // 8 halves
            const __half2* hp = reinterpret_cast<const __half2*>(&raw);
            float2 f0 = __half22float2(hp[0]);
            float2 f1 = __half22float2(hp[1]);
            float2 f2 = __half22float2(hp[2]);
            float2 f3 = __half22float2(hp[3]);
            float sv = LN ? (sj * inv) : sj;
            if (LN) {
                acc[0] = fmaf(f0.x - mu, sv, acc[0]); acc[1] = fmaf(f0.y - mu, sv, acc[1]);
                acc[2] = fmaf(f1.x - mu, sv, acc[2]); acc[3] = fmaf(f1.y - mu, sv, acc[3]);
                acc[4] = fmaf(f2.x - mu, sv, acc[4]); acc[5] = fmaf(f2.y - mu, sv, acc[5]);
                acc[6] = fmaf(f3.x - mu, sv, acc[6]); acc[7] = fmaf(f3.y - mu, sv, acc[7]);
            } else {
                acc[0] = fmaf(f0.x, sv, acc[0]); acc[1] = fmaf(f0.y, sv, acc[1]);
                acc[2] = fmaf(f1.x, sv, acc[2]); acc[3] = fmaf(f1.y, sv, acc[3]);
                acc[4] = fmaf(f2.x, sv, acc[4]); acc[5] = fmaf(f2.y, sv, acc[5]);
                acc[6] = fmaf(f3.x, sv, acc[6]); acc[7] = fmaf(f3.y, sv, acc[7]);
            }
        }
    }
    float nd = g_norm_d[gw];
    __half2 hv[4];
    hv[0] = __floats2half2_rn(acc[0] * nd, acc[1] * nd);
    hv[1] = __floats2half2_rn(acc[2] * nd, acc[3] * nd);
    hv[2] = __floats2half2_rn(acc[4] * nd, acc[5] * nd);
    hv[3] = __floats2half2_rn(acc[6] * nd, acc[7] * nd);
    reinterpret_cast<float4*>(out)[(size_t)gw * 32 + lane] = *reinterpret_cast<float4*>(hv);
}

// ---------------- SpMM 64-wide (final layer, fp16 gather, with bias) ----------------
__global__ void k_spmm64(const __half* __restrict__ tin, const float* __restrict__ bias,
                         float* __restrict__ out) {
    int gw = (blockIdx.x * blockDim.x + threadIdx.x) >> 5;
    int lane = threadIdx.x & 31;
    if (gw >= NN_NODES) return;

    int s0 = g_row_off[gw], s1 = g_row_off[gw + 1];
    float2 a = make_float2(0.f, 0.f);
    const __half2* __restrict__ t2 = reinterpret_cast<const __half2*>(tin);

    for (int base = s0; base < s1; base += 32) {
        int kk = base + lane;
        int j = 0; float sc = 0.f;
        if (kk < s1) {
            int2 e = g_edge[kk];
            j = e.x; sc = __int_as_float(e.y);
        }
        int cnt = min(32, s1 - base);
#pragma unroll 8
        for (int i = 0; i < cnt; i++) {
            int   jj = __shfl_sync(0xffffffffu, j, i);
            float sj = __shfl_sync(0xffffffffu, sc, i);
            float2 v = __half22float2(t2[(size_t)jj * (CDIM / 2) + lane]);
            a.x = fmaf(v.x, sj, a.x);
            a.y = fmaf(v.y, sj, a.y);
        }
    }
    float nd = g_norm_d[gw];
    float2 b = reinterpret_cast<const float2*>(bias)[lane];
    float2 o;
    o.x = fmaf(a.x, nd, b.x);
    o.y = fmaf(a.y, nd, b.y);
    reinterpret_cast<float2*>(out)[(size_t)gw * (CDIM / 2) + lane] = o;
}

// ---------------- fp16 tensor-core GEMM: A fp16 (pure copy), B pre-split (exact) ----------------
// C = A @ W, 2 MMAs per frag pair: Ah*Bh + Ah*Bl.
template <int BM, int BN, int WM, int WN, bool BIAS_RELU, bool STATS, bool LNFOLD,
          bool C_HALF>
__global__ void __launch_bounds__(256, 2)
k_gemm16(const __half* __restrict__ A16,
         const __half* __restrict__ Bh_g,   // [n][K] fp16 hi
         const __half* __restrict__ Bl_g,   // [n][K] fp16 lo
         const float* __restrict__ bias, void* __restrict__ Cp,
         int M, int Nn, int K) {
    constexpr int BK = 32;
    constexpr int LDA = BK + 8;          // halves; pitch 80B
    constexpr int LDB = BK + 8;
    constexpr int NWARP = (BM / WM) * (BN / WN);
    constexpr int NT = NWARP * 32;
    constexpr int MFRAG = WM / 16;
    constexpr int NFRAG = WN / 8;
    static_assert(BM * (BK / 16) == NT, "A staging map");

    __shared__ __half As[BM * LDA];
    __shared__ __half Bs_h[BN * LDB];
    __shared__ __half Bs_l[BN * LDB];

    const int tid  = threadIdx.x;
    const int lane = tid & 31;
    const int warp = tid >> 5;
    const int wm0 = (warp / (BN / WN)) * WM;
    const int wn0 = (warp % (BN / WN)) * WN;
    const int bm0 = blockIdx.x * BM;
    const int bn0 = blockIdx.y * BN;

    float acc[MFRAG][NFRAG][4];
#pragma unroll
    for (int i = 0; i < MFRAG; i++)
#pragma unroll
        for (int j = 0; j < NFRAG; j++)
#pragma unroll
            for (int q = 0; q < 4; q++) acc[i][j][q] = 0.f;

    const int gr = lane >> 2;
    const int gc = lane & 3;

    // A staging: 2 threads per row, 16 consecutive halves (32B) each — pure copy
    const int am = tid >> 1;
    const int aq = tid & 1;
    const int arow = bm0 + am;
    const bool aok = arow < M;

    for (int k0 = 0; k0 < K; k0 += BK) {
        // ---- stage A: float4 copies ----
        {
            uint4 v0 = make_uint4(0u, 0u, 0u, 0u), v1 = v0;
            if (aok) {
                const uint4* s = reinterpret_cast<const uint4*>(&A16[(size_t)arow * K + k0 + aq * 16]);
                v0 = s[0]; v1 = s[1];
            }
            uint4* pa = reinterpret_cast<uint4*>(&As[am * LDA + aq * 16]);
            pa[0] = v0; pa[1] = v1;
        }
        // ---- stage B: float4 copies from pre-split [n][K] fp16 ----
        constexpr int B4 = BN * BK / 8;   // float4 count
#pragma unroll
        for (int p = 0; p < B4 / NT; p++) {
            int idx = tid + p * NT;
            int n = idx / (BK / 8), seg = idx % (BK / 8);
            size_t goff = (size_t)(bn0 + n) * K + k0 + seg * 8;
            *reinterpret_cast<uint4*>(&Bs_h[n * LDB + seg * 8]) =
                *reinterpret_cast<const uint4*>(&Bh_g[goff]);
            *reinterpret_cast<uint4*>(&Bs_l[n * LDB + seg * 8]) =
                *reinterpret_cast<const uint4*>(&Bl_g[goff]);
        }
        __syncthreads();

#pragma unroll
        for (int ks = 0; ks < BK / 16; ks++) {
            const int kb = ks * 16;
            unsigned a[MFRAG][4];
#pragma unroll
            for (int mi = 0; mi < MFRAG; mi++) {
                int r = wm0 + mi * 16 + gr;
                a[mi][0] = *reinterpret_cast<const unsigned*>(&As[r * LDA + kb + 2 * gc]);
                a[mi][1] = *reinterpret_cast<const unsigned*>(&As[(r + 8) * LDA + kb + 2 * gc]);
                a[mi][2] = *reinterpret_cast<const unsigned*>(&As[r * LDA + kb + 2 * gc + 8]);
                a[mi][3] = *reinterpret_cast<const unsigned*>(&As[(r + 8) * LDA + kb + 2 * gc + 8]);
            }
            unsigned bh[NFRAG][2], bl[NFRAG][2];
#pragma unroll
            for (int ni = 0; ni < NFRAG; ni++) {
                int c = wn0 + ni * 8 + gr;
                bh[ni][0] = *reinterpret_cast<const unsigned*>(&Bs_h[c * LDB + kb + 2 * gc]);
                bh[ni][1] = *reinterpret_cast<const unsigned*>(&Bs_h[c * LDB + kb + 2 * gc + 8]);
                bl[ni][0] = *reinterpret_cast<const unsigned*>(&Bs_l[c * LDB + kb + 2 * gc]);
                bl[ni][1] = *reinterpret_cast<const unsigned*>(&Bs_l[c * LDB + kb + 2 * gc + 8]);
            }
#pragma unroll
            for (int mi = 0; mi < MFRAG; mi++)
#pragma unroll
                for (int ni = 0; ni < NFRAG; ni++) {
#define MMA_F16(B0,B1)                                                           \
    asm volatile("mma.sync.aligned.m16n8k16.row.col.f32.f16.f16.f32 "            \
                 "{%0,%1,%2,%3}, {%4,%5,%6,%7}, {%8,%9}, {%0,%1,%2,%3};"         \
                 : "+f"(acc[mi][ni][0]), "+f"(acc[mi][ni][1]),                   \
                   "+f"(acc[mi][ni][2]), "+f"(acc[mi][ni][3])                    \
                 : "r"(a[mi][0]), "r"(a[mi][1]), "r"(a[mi][2]), "r"(a[mi][3]),   \
                   "r"(B0), "r"(B1))
                    MMA_F16(bl[ni][0], bl[ni][1]);
                    MMA_F16(bh[ni][0], bh[ni][1]);
#undef MMA_F16
                }
        }
        __syncthreads();
    }

    // ---- epilogue ----
    float mu = 0.f, inv = 1.f;
    if (LNFOLD) { mu = g_ln[0]; inv = g_ln[1]; }
    double psum = 0.0, psq = 0.0;
#pragma unroll
    for (int mi = 0; mi < MFRAG; mi++) {
#pragma unroll
        for (int ni = 0; ni < NFRAG; ni++) {
            int c0 = bn0 + wn0 + ni * 8 + gc * 2;
            float2 bb = make_float2(0.f, 0.f);
            if (BIAS_RELU) bb = *reinterpret_cast<const float2*>(&bias[c0]);
            float2 cs = make_float2(0.f, 0.f);
            if (LNFOLD) cs = *reinterpret_cast<const float2*>(&g_csum[c0]);
#pragma unroll
            for (int hf = 0; hf < 2; hf++) {
                int row = bm0 + wm0 + mi * 16 + gr + hf * 8;
                if (row >= M) continue;
                float x = acc[mi][ni][hf * 2 + 0];
                float y = acc[mi][ni][hf * 2 + 1];
                if (BIAS_RELU) {
                    x = fmaxf(x + bb.x, 0.f);
                    y = fmaxf(y + bb.y, 0.f);
                }
                if (LNFOLD) {
                    x = x * inv - mu * inv * cs.x;
                    y = y * inv - mu * inv * cs.y;
                }
                if (C_HALF) {
                    __half* C16 = (__half*)Cp;
                    *reinterpret_cast<__half2*>(&C16[(size_t)row * Nn + c0]) =
                        __floats2half2_rn(x, y);
                } else {
                    float* Cf = (float*)Cp;
                    *reinterpret_cast<float2*>(&Cf[(size_t)row * Nn + c0]) = make_float2(x, y);
                }
                if (STATS) {
                    psum += (double)x + (double)y;
                    psq  += (double)x * x + (double)y * y;
                }
            }
        }
    }

    if (STATS) {
#pragma unroll
        for (int off = 16; off > 0; off >>= 1) {
            psum += __shfl_down_sync(0xffffffffu, psum, off);
            psq  += __shfl_down_sync(0xffffffffu, psq, off);
        }
        if (lane == 0) {
            atomicAdd(&g_stats[0], psum);
            atomicAdd(&g_stats[1], psq);
        }
    }
}

__global__ void k_finalize(double count) {
    double s = g_stats[0], ss = g_stats[1];
    double mu = s / count;
    double var = ss / count - mu * mu;
    g_ln[0] = (float)mu;
    g_ln[1] = (float)(1.0 / sqrt(var + (double)LN_EPS));
    g_stats[0] = 0.0;
    g_stats[1] = 0.0;
}

// ---------------- launch ----------------
extern "C" void kernel_launch(void* const* d_in, const int* in_sizes, int n_in,
                              void* d_out, int out_size) {
    const float* feat = (const float*)d_in[0];
    const int*   src  = (const int*)d_in[1];
    const int*   dst  = (const int*)d_in[2];
    const float* W0   = (const float*)d_in[3];
    const float* b0   = (const float*)d_in[4];
    const float* W1   = (const float*)d_in[5];
    const float* b1   = (const float*)d_in[6];
    const float* W2   = (const float*)d_in[7];
    const float* b2   = (const float*)d_in[8];
    float* out = (float*)d_out;

    __half *x16, *h16, *agg16, *tbuf;
    __half *w0h, *w0l, *w1h, *w1l, *w2h, *w2l;
    cudaGetSymbolAddress((void**)&x16, g_x16);
    cudaGetSymbolAddress((void**)&h16, g_h16);
    cudaGetSymbolAddress((void**)&agg16, g_agg16);
    cudaGetSymbolAddress((void**)&tbuf, g_t16);
    cudaGetSymbolAddress((void**)&w0h, g_w0h);
    cudaGetSymbolAddress((void**)&w0l, g_w0l);
    cudaGetSymbolAddress((void**)&w1h, g_w1h);
    cudaGetSymbolAddress((void**)&w1l, g_w1l);
    cudaGetSymbolAddress((void**)&w2h, g_w2h);
    cudaGetSymbolAddress((void**)&w2l, g_w2l);

    const int NB_N = (NN_NODES + 255) / 256;
    const int NB_E4 = ((EE_EDGES / 4) + 255) / 256;  // ILP-4 edge kernels
    const int NB_W = (NN_NODES * 32 + 255) / 256;    // warp per row
    const int NB_C = ((NN_NODES * FDIM / 8) + 255) / 256;

    // setup: degrees, multi-block scan, CSR with packed payload, fp16 features, split weights
    k_init<<<NB_N, 256>>>();
    k_degrees<<<NB_E4, 256>>>(src, dst);
    k_scan1<<<NTILES, TILE>>>();
    k_scan2<<<1, 512>>>();
    k_scan3<<<NTILES, TILE>>>();
    k_fill<<<NB_E4, 256>>>(src, dst);
    k_cvt<<<NB_C, 256>>>(feat, x16, NN_NODES * FDIM / 8);
    k_prep_w<<<(FDIM * FDIM + 255) / 256, 256>>>(W0, w0h, w0l, FDIM, FDIM);
    k_prep_w<<<(FDIM * FDIM + 255) / 256, 256>>>(W1, w1h, w1l, FDIM, FDIM);
    k_prep_w<<<(FDIM * CDIM + 255) / 256, 256>>>(W2, w2h, w2l, FDIM, CDIM);
    k_csum<<<CDIM, FDIM>>>(W2);

    const int GM = (NN_NODES + 127) / 128;
    const double cnt = (double)NN_NODES * FDIM;

    // layer 1: agg16 = fp16(DAD*X) ; h1 = relu(agg@W0 + b0) (+stats), fp16
    k_spmm256<false><<<NB_W, 256>>>(x16, agg16);
    k_gemm16<128, 128, 64, 32, true, true, false, true>
        <<<dim3(GM, FDIM / 128), 256>>>(agg16, w0h, w0l, b0, h16, NN_NODES, FDIM, FDIM);
    k_finalize<<<1, 1>>>(cnt);

    // layer 2: agg16 = fp16(DAD*LN(h1)) ; h2 = relu(agg@W1 + b1) (+stats), fp16
    k_spmm256<true><<<NB_W, 256>>>(h16, agg16);
    k_gemm16<128, 128, 64, 32, true, true, false, true>
        <<<dim3(GM, FDIM / 128), 256>>>(agg16, w1h, w1l, b1, h16, NN_NODES, FDIM, FDIM);
    k_finalize<<<1, 1>>>(cnt);

    // layer 3: t16 = fp16(LN(h2)@W2) via epilogue fold ; out = DAD*t + b2
    k_gemm16<128, 64, 64, 16, false, false, true, true>
        <<<dim3(GM, 1), 256>>>(h16, w2h, w2l, nullptr, tbuf, NN_NODES, CDIM, FDIM);
    k_spmm64<<<NB_W, 256>>>(tbuf, b2, out);
}